// round 4
// baseline (speedup 1.0000x reference)
#include <cuda_runtime.h>
#include <math.h>

#define N_NODES 50000
#define N_EDGES 800000
#define NHEADS  8
#define MULT    16
#define BUCKET  64     // max in-degree capacity; Poisson(16) tail @64 ~ 1e-20

// Scratch (device globals — no allocation allowed)
__device__ float g_e[(size_t)N_EDGES * NHEADS];        // exp scores (25.6 MB)
__device__ float g_s[(size_t)N_NODES * NHEADS];        // denoms -> inverted (1.6 MB)
__device__ int   g_cnt[N_NODES];                       // per-col edge counts
__device__ int   g_bucket[(size_t)N_NODES * BUCKET];   // edge ids per col (12.8 MB)

// ---------------------------------------------------------------------------
// Pass 1: FOUR threads per edge, thread q owns heads {2q, 2q+1}.
// All k/q traffic via LDG.128. Thread q==0 also appends edge id to its
// col bucket (replaces CSR build — no scans needed).
// ---------------------------------------------------------------------------
__global__ void __launch_bounds__(256) pass1_scores(
    const float* __restrict__ k0, const float* __restrict__ k1,
    const float* __restrict__ q0, const float* __restrict__ q1,
    const int* __restrict__ row_idx, const int* __restrict__ col_idx)
{
    int t = blockIdx.x * blockDim.x + threadIdx.x;
    if (t >= N_EDGES * 4) return;
    int e = t >> 2;
    int q = t & 3;

    int col = __ldg(col_idx + e);
    int rw  = __ldg(row_idx + e);

    // k0/q0: heads 2q,2q+1 = flat floats [4q..4q+3]
    float4 ka = __ldg((const float4*)(k0 + (size_t)e   * 16 + 4 * q));
    float4 qa = __ldg((const float4*)(q0 + (size_t)col * 16 + 4 * q));
    // k1/q1: flat floats [12q..12q+11]; head 2q = first 6, head 2q+1 = last 6
    const float4* kb = (const float4*)(k1 + (size_t)e   * 48 + 12 * q);
    const float4* qb = (const float4*)(q1 + (size_t)col * 48 + 12 * q);
    float4 b0 = __ldg(kb);     float4 c0 = __ldg(qb);
    float4 b1 = __ldg(kb + 1); float4 c1 = __ldg(qb + 1);
    float4 b2 = __ldg(kb + 2); float4 c2 = __ldg(qb + 2);

    float d0 = ka.x * qa.x + ka.y * qa.y
             + b0.x * c0.x + b0.y * c0.y + b0.z * c0.z + b0.w * c0.w
             + b1.x * c1.x + b1.y * c1.y;
    float d1 = ka.z * qa.z + ka.w * qa.w
             + b1.z * c1.z + b1.w * c1.w
             + b2.x * c2.x + b2.y * c2.y + b2.z * c2.z + b2.w * c2.w;

    float w0 = expf(d0 * 0.125f);   // 1/sqrt(64)
    float w1 = expf(d1 * 0.125f);

    *(float2*)(g_e + (size_t)e * NHEADS + 2 * q) = make_float2(w0, w1);

    float* sp = g_s + (size_t)rw * NHEADS + 2 * q;
    asm volatile("red.global.add.v2.f32 [%0], {%1, %2};"
                 :: "l"(sp), "f"(w0), "f"(w1) : "memory");

    if (q == 0) {
        int slot = atomicAdd(&g_cnt[col], 1);
        if (slot < BUCKET) g_bucket[(size_t)col * BUCKET + slot] = e;
    }
}

// ---------------------------------------------------------------------------
// Invert denominators once.
// ---------------------------------------------------------------------------
__global__ void __launch_bounds__(256) invert_s()
{
    int t = blockIdx.x * blockDim.x + threadIdx.x;
    if (t >= N_NODES * NHEADS) return;
    float s = g_s[t];
    g_s[t] = (s > 0.0f) ? (1.0f / s) : 0.0f;
}

// ---------------------------------------------------------------------------
// Gather accumulate for one edge into this thread's float4 chunk.
// j < 4:  out0 chunk j   (heads 2j, 2j+1)
// j >= 4: out1 chunk f0=4(j-4), heads f/6
// ---------------------------------------------------------------------------
__device__ __forceinline__ void acc_edge(
    int e, int j,
    const float* __restrict__ v0, const float* __restrict__ v1,
    const int* __restrict__ row_idx, float4& acc)
{
    int rw = __ldg(row_idx + e);
    const float* eb = g_e + (size_t)e  * NHEADS;
    const float* sb = g_s + (size_t)rw * NHEADS;

    if (j < 4) {
        float2 ew = *(const float2*)(eb + 2 * j);
        float2 sw = *(const float2*)(sb + 2 * j);
        float a0 = ew.x * sw.x;
        float a1 = ew.y * sw.y;
        float4 v = __ldg((const float4*)(v0 + (size_t)e * 16 + 4 * j));
        acc.x += v.x * a0;
        acc.y += v.y * a0;
        acc.z += v.z * a1;
        acc.w += v.w * a1;
    } else {
        int f0 = 4 * (j - 4);
        int hlo = f0 / 6;
        int hhi = (f0 + 3) / 6;
        float alo = __ldg(eb + hlo) * __ldg(sb + hlo);
        float ahi = (hhi == hlo) ? alo : __ldg(eb + hhi) * __ldg(sb + hhi);
        float4 v = __ldg((const float4*)(v1 + (size_t)e * 48 + f0));
        acc.x += v.x * (((f0 + 0) / 6 == hlo) ? alo : ahi);
        acc.y += v.y * (((f0 + 1) / 6 == hlo) ? alo : ahi);
        acc.z += v.z * (((f0 + 2) / 6 == hlo) ? alo : ahi);
        acc.w += v.w * (((f0 + 3) / 6 == hlo) ? alo : ahi);
    }
}

// ---------------------------------------------------------------------------
// Gather: 16 threads per destination node, each owns one output float4.
// Edges processed 4 at a time (int4 bucket read) for MLP. No atomics.
// ---------------------------------------------------------------------------
__global__ void __launch_bounds__(256) gather(
    const float* __restrict__ v0, const float* __restrict__ v1,
    const int* __restrict__ row_idx,
    float* __restrict__ out0, float* __restrict__ out1)
{
    int tid = threadIdx.x;
    int j = tid & 15;
    int n = blockIdx.x * 16 + (tid >> 4);   // 3125 * 16 = 50000 exactly

    int cnt = __ldg(&g_cnt[n]);
    if (cnt > BUCKET) cnt = BUCKET;
    const int* bucket = g_bucket + (size_t)n * BUCKET;

    float4 acc = make_float4(0.f, 0.f, 0.f, 0.f);

    for (int i = 0; i < cnt; i += 4) {
        int4 eq = *(const int4*)(bucket + i);   // 16B-aligned (i % 4 == 0)
        int m = cnt - i;
        acc_edge(eq.x, j, v0, v1, row_idx, acc);
        if (m > 1) acc_edge(eq.y, j, v0, v1, row_idx, acc);
        if (m > 2) acc_edge(eq.z, j, v0, v1, row_idx, acc);
        if (m > 3) acc_edge(eq.w, j, v0, v1, row_idx, acc);
    }

    if (j < 4) {
        *(float4*)(out0 + (size_t)n * 16 + 4 * j) = acc;
    } else {
        int f0 = 4 * (j - 4);
        *(float4*)(out1 + (size_t)n * 48 + f0) = acc;
    }
}

// ---------------------------------------------------------------------------
// Launch.  Inputs: v0, v1, k0, k1, q0, q1, edge_index
// Output: out0 (N*16) ++ out1 (N*48)
// ---------------------------------------------------------------------------
extern "C" void kernel_launch(void* const* d_in, const int* in_sizes, int n_in,
                              void* d_out, int out_size)
{
    const float* v0 = (const float*)d_in[0];
    const float* v1 = (const float*)d_in[1];
    const float* k0 = (const float*)d_in[2];
    const float* k1 = (const float*)d_in[3];
    const float* q0 = (const float*)d_in[4];
    const float* q1 = (const float*)d_in[5];
    const int*   ei = (const int*)  d_in[6];
    const int* row_idx = ei;             // edge_index[0]
    const int* col_idx = ei + N_EDGES;   // edge_index[1]

    float* out0 = (float*)d_out;
    float* out1 = out0 + (size_t)N_NODES * MULT;

    void* s_addr = nullptr;
    void* c_addr = nullptr;
    cudaGetSymbolAddress(&s_addr, g_s);
    cudaGetSymbolAddress(&c_addr, g_cnt);

    cudaMemsetAsync(s_addr, 0, (size_t)N_NODES * NHEADS * sizeof(float));
    cudaMemsetAsync(c_addr, 0, (size_t)N_NODES * sizeof(int));
    // no output memset needed — gather writes every output element

    int n1 = N_EDGES * 4;
    pass1_scores<<<(n1 + 255) / 256, 256>>>(k0, k1, q0, q1, row_idx, col_idx);

    int ns = N_NODES * NHEADS;
    invert_s<<<(ns + 255) / 256, 256>>>();

    gather<<<N_NODES / 16, 256>>>(v0, v1, row_idx, out0, out1);
}

// round 5
// speedup vs baseline: 1.6028x; 1.6028x over previous
#include <cuda_runtime.h>
#include <math.h>

#define N_NODES 50000
#define N_EDGES 800000
#define NHEADS  8
#define MULT    16

// Scratch (device globals — no allocation allowed)
__device__ float g_e[(size_t)N_EDGES * NHEADS];   // exp scores (25.6 MB)
__device__ float g_s[(size_t)N_NODES * NHEADS];   // softmax denominators (1.6 MB)

// ---------------------------------------------------------------------------
// Pass 1: one (edge, head) element per slot, TWO slots per thread (ILP x2,
// stride = total/2 keeps both halves warp-coalesced). Proven 8-slots/edge
// float2 mapping; the x2 ILP doubles outstanding loads per thread to cover
// L2 latency on the random q[col] gathers.
// ---------------------------------------------------------------------------
__global__ void __launch_bounds__(256) pass1_scores(
    const float* __restrict__ k0, const float* __restrict__ k1,
    const float* __restrict__ q0, const float* __restrict__ q1,
    const int* __restrict__ row_idx, const int* __restrict__ col_idx)
{
    const int HALF = N_EDGES * NHEADS / 2;   // 3.2M
    int t = blockIdx.x * blockDim.x + threadIdx.x;
    if (t >= HALF) return;

    int tA = t;
    int tB = t + HALF;
    int eA = tA >> 3, hA = tA & 7;
    int eB = tB >> 3, hB = tB & 7;   // == hA (HALF % 8 == 0), kept for clarity

    // Issue both index loads first
    int colA = __ldg(col_idx + eA);
    int colB = __ldg(col_idx + eB);
    int rwA  = __ldg(row_idx + eA);
    int rwB  = __ldg(row_idx + eB);

    // Independent load streams for A and B
    float2 kaA = *(const float2*)(k0 + (size_t)eA   * 16 + 2 * hA);
    float2 kaB = *(const float2*)(k0 + (size_t)eB   * 16 + 2 * hB);
    float2 qaA = *(const float2*)(q0 + (size_t)colA * 16 + 2 * hA);
    float2 qaB = *(const float2*)(q0 + (size_t)colB * 16 + 2 * hB);

    const float2* k1A = (const float2*)(k1 + (size_t)eA   * 48 + 6 * hA);
    const float2* q1A = (const float2*)(q1 + (size_t)colA * 48 + 6 * hA);
    const float2* k1B = (const float2*)(k1 + (size_t)eB   * 48 + 6 * hB);
    const float2* q1B = (const float2*)(q1 + (size_t)colB * 48 + 6 * hB);

    float2 kA0 = k1A[0], kA1 = k1A[1], kA2 = k1A[2];
    float2 qA0 = q1A[0], qA1 = q1A[1], qA2 = q1A[2];
    float2 kB0 = k1B[0], kB1 = k1B[1], kB2 = k1B[2];
    float2 qB0 = q1B[0], qB1 = q1B[1], qB2 = q1B[2];

    float dA = kaA.x * qaA.x + kaA.y * qaA.y
             + kA0.x * qA0.x + kA0.y * qA0.y
             + kA1.x * qA1.x + kA1.y * qA1.y
             + kA2.x * qA2.x + kA2.y * qA2.y;
    float dB = kaB.x * qaB.x + kaB.y * qaB.y
             + kB0.x * qB0.x + kB0.y * qB0.y
             + kB1.x * qB1.x + kB1.y * qB1.y
             + kB2.x * qB2.x + kB2.y * qB2.y;

    float wA = expf(dA * 0.125f);   // 1/sqrt(64)
    float wB = expf(dB * 0.125f);

    g_e[tA] = wA;
    g_e[tB] = wB;

    atomicAdd(&g_s[rwA * NHEADS + hA], wA);
    atomicAdd(&g_s[rwB * NHEADS + hB], wB);
}

// ---------------------------------------------------------------------------
// Pass 2: FOUR threads per edge (R3's proven winner). Thread q owns heads
// {2q, 2q+1}. Denominator inversion fused here via MUFU reciprocal (the
// standalone invert kernel is gone). 4 vector REDs per thread.
// Any s read here belongs to a row with >=1 edge, so s > 0 always.
// ---------------------------------------------------------------------------
__global__ void __launch_bounds__(256) pass2_scatter(
    const float* __restrict__ v0, const float* __restrict__ v1,
    const int* __restrict__ row_idx, const int* __restrict__ col_idx,
    float* __restrict__ out0, float* __restrict__ out1)
{
    int t = blockIdx.x * blockDim.x + threadIdx.x;
    if (t >= N_EDGES * 4) return;
    int e = t >> 2;
    int q = t & 3;

    int rw  = __ldg(row_idx + e);
    int col = __ldg(col_idx + e);

    float2 ew = *(const float2*)(g_e + (size_t)e  * NHEADS + 2 * q);
    float2 sw = *(const float2*)(g_s + (size_t)rw * NHEADS + 2 * q);
    float a0 = ew.x * __fdividef(1.0f, sw.x);   // head 2q
    float a1 = ew.y * __fdividef(1.0f, sw.y);   // head 2q+1

    // ---- out0 chunk q: v0 floats 4q..4q+3, heads {2q,2q,2q+1,2q+1} ----
    {
        float4 v = __ldg((const float4*)(v0 + (size_t)e * 16 + 4 * q));
        float* p = out0 + (size_t)col * 16 + 4 * q;
        asm volatile("red.global.add.v4.f32 [%0], {%1, %2, %3, %4};"
                     :: "l"(p), "f"(v.x * a0), "f"(v.y * a0),
                        "f"(v.z * a1), "f"(v.w * a1) : "memory");
    }

    // ---- out1 chunks 3q..3q+2: v1 floats 12q..12q+11 ----
    const float* vb = v1 + (size_t)e * 48 + 12 * q;
    float* pb = out1 + (size_t)col * 48 + 12 * q;

    {
        float4 v = __ldg((const float4*)(vb));        // all head 2q
        asm volatile("red.global.add.v4.f32 [%0], {%1, %2, %3, %4};"
                     :: "l"(pb), "f"(v.x * a0), "f"(v.y * a0),
                        "f"(v.z * a0), "f"(v.w * a0) : "memory");
    }
    {
        float4 v = __ldg((const float4*)(vb + 4));    // a0,a0,a1,a1
        asm volatile("red.global.add.v4.f32 [%0], {%1, %2, %3, %4};"
                     :: "l"(pb + 4), "f"(v.x * a0), "f"(v.y * a0),
                        "f"(v.z * a1), "f"(v.w * a1) : "memory");
    }
    {
        float4 v = __ldg((const float4*)(vb + 8));    // all head 2q+1
        asm volatile("red.global.add.v4.f32 [%0], {%1, %2, %3, %4};"
                     :: "l"(pb + 8), "f"(v.x * a1), "f"(v.y * a1),
                        "f"(v.z * a1), "f"(v.w * a1) : "memory");
    }
}

// ---------------------------------------------------------------------------
// Launch.  Inputs: v0, v1, k0, k1, q0, q1, edge_index
// Output: out0 (N*16) ++ out1 (N*48)
// ---------------------------------------------------------------------------
extern "C" void kernel_launch(void* const* d_in, const int* in_sizes, int n_in,
                              void* d_out, int out_size)
{
    const float* v0 = (const float*)d_in[0];
    const float* v1 = (const float*)d_in[1];
    const float* k0 = (const float*)d_in[2];
    const float* k1 = (const float*)d_in[3];
    const float* q0 = (const float*)d_in[4];
    const float* q1 = (const float*)d_in[5];
    const int*   ei = (const int*)  d_in[6];
    const int* row_idx = ei;             // edge_index[0]
    const int* col_idx = ei + N_EDGES;   // edge_index[1]

    float* out0 = (float*)d_out;
    float* out1 = out0 + (size_t)N_NODES * MULT;

    void* s_addr = nullptr;
    cudaGetSymbolAddress(&s_addr, g_s);

    cudaMemsetAsync(s_addr, 0, (size_t)N_NODES * NHEADS * sizeof(float));
    cudaMemsetAsync(d_out, 0, (size_t)out_size * sizeof(float));

    int half = N_EDGES * NHEADS / 2;
    pass1_scores<<<(half + 255) / 256, 256>>>(k0, k1, q0, q1, row_idx, col_idx);

    int n2 = N_EDGES * 4;
    pass2_scatter<<<(n2 + 255) / 256, 256>>>(v0, v1, row_idx, col_idx, out0, out1);
}